// round 15
// baseline (speedup 1.0000x reference)
#include <cuda_runtime.h>

// ---------------- problem-size constants (fixed by the dataset) ----------
#define MAXN 50000
#define MAXE 800000
#define MAXET (MAXN + MAXE)

// ---------------- scratch (device globals; no allocation allowed) --------
__device__ int   g_src[MAXET];
__device__ int   g_dst[MAXET];
__device__ int   g_csr[MAXET];
__device__ int   g_count[MAXN];
__device__ int   g_rowoff[MAXN + 1];
__device__ int   g_cursor[MAXN];
__device__ float g_h1[(size_t)MAXN * 256];
__device__ float g_agg1[(size_t)MAXN * 256];
__device__ float g_als1[MAXN * 4];
__device__ float g_ald1[MAXN * 4];
__device__ float g_h2[(size_t)MAXN * 64];
__device__ float g_agg2[(size_t)MAXN * 64];
__device__ float g_als2[MAXN];
__device__ float g_ald2[MAXN];

#define NEG_SLOPE 0.2f
#define LN_EPS 1e-5f

// ---------------- helpers -------------------------------------------------
__device__ __forceinline__ float lrelu(float v) { return v > 0.f ? v : NEG_SLOPE * v; }
__device__ __forceinline__ float wredmax(float v) {
    #pragma unroll
    for (int o = 16; o; o >>= 1) v = fmaxf(v, __shfl_xor_sync(0xffffffffu, v, o));
    return v;
}
__device__ __forceinline__ float wredsum(float v) {
    #pragma unroll
    for (int o = 16; o; o >>= 1) v += __shfl_xor_sync(0xffffffffu, v, o);
    return v;
}

// ---------------- graph prep ----------------------------------------------
__global__ void zero_int_kernel(int* __restrict__ p, int n) {
    int i = blockIdx.x * blockDim.x + threadIdx.x;
    if (i < n) p[i] = 0;
}

// edge_index may be int64 (values < 2^31, high words 0) or int32. Detect by
// checking 16 odd int32 positions: all-zero <=> int64 (prob ~0 for real data).
__global__ void prep_edges_kernel(const int* __restrict__ ei32, int E, int N) {
    int i = blockIdx.x * blockDim.x + threadIdx.x;
    int ET = E + N;
    if (i >= ET) return;
    bool is64 = true;
    #pragma unroll
    for (int t = 1; t <= 31; t += 2) is64 = is64 && (ei32[t] == 0);
    int s, d;
    if (i < E) {
        if (is64) { s = ei32[2 * i];     d = ei32[2 * (E + i)]; }
        else      { s = ei32[i];         d = ei32[E + i]; }
    } else {
        s = d = i - E;  // self-loops appended (PyG add_self_loops)
    }
    g_src[i] = s;
    g_dst[i] = d;
    atomicAdd(&g_count[d], 1);
}

// single-block exclusive scan of counts -> rowoff + cursor copy
__global__ void scan_kernel(int N, int ET) {
    __shared__ int s[1024];
    int t = threadIdx.x;
    int chunk = (N + 1023) / 1024;
    int b = t * chunk;
    int e = min(N, b + chunk);
    int sum = 0;
    for (int i = b; i < e; i++) sum += g_count[i];
    s[t] = sum;
    __syncthreads();
    for (int o = 1; o < 1024; o <<= 1) {
        int v = (t >= o) ? s[t - o] : 0;
        __syncthreads();
        s[t] += v;
        __syncthreads();
    }
    int run = (t > 0) ? s[t - 1] : 0;
    for (int i = b; i < e; i++) {
        g_rowoff[i] = run;
        g_cursor[i] = run;
        run += g_count[i];
    }
    if (t == 1023) g_rowoff[N] = s[1023];
}

__global__ void scatter_kernel(int ET) {
    int i = blockIdx.x * blockDim.x + threadIdx.x;
    if (i >= ET) return;
    int d = g_dst[i];
    int pos = atomicAdd(&g_cursor[d], 1);
    g_csr[pos] = g_src[i];
}

// ---------------- fp32 tiled SGEMM: C[M,Nn] = A[M,K] @ B[K,Nn] ------------
__global__ __launch_bounds__(256) void sgemm_128x64_kernel(
    const float* __restrict__ A, const float* __restrict__ B,
    float* __restrict__ C, int M, int K, int Nn) {
    const int BM = 128, BN = 64, BK = 16;
    __shared__ __align__(16) float As[BK][BM];
    __shared__ __align__(16) float Bs[BK][BN];
    int tid = threadIdx.x;
    int tx = tid & 15, ty = tid >> 4;
    int m0 = blockIdx.x * BM, n0 = blockIdx.y * BN;

    float4 acc[8];
    #pragma unroll
    for (int i = 0; i < 8; i++) acc[i] = make_float4(0.f, 0.f, 0.f, 0.f);

    for (int k0 = 0; k0 < K; k0 += BK) {
        // load A tile (transposed into As[k][m]); 2 float4 per thread
        #pragma unroll
        for (int r = 0; r < 2; r++) {
            int f = tid + r * 256;       // float4 index, tile layout [128][4]
            int row = f >> 2;
            int kq = f & 3;
            float4 v = make_float4(0.f, 0.f, 0.f, 0.f);
            if (m0 + row < M)
                v = *(const float4*)(A + (size_t)(m0 + row) * K + k0 + kq * 4);
            As[kq * 4 + 0][row] = v.x;
            As[kq * 4 + 1][row] = v.y;
            As[kq * 4 + 2][row] = v.z;
            As[kq * 4 + 3][row] = v.w;
        }
        {   // load B tile [16][64]; 1 float4 per thread
            int kk = tid >> 4;
            int nq = tid & 15;
            *(float4*)(&Bs[kk][nq * 4]) =
                *(const float4*)(B + (size_t)(k0 + kk) * Nn + n0 + nq * 4);
        }
        __syncthreads();
        #pragma unroll
        for (int k = 0; k < BK; k++) {
            float4 a0 = *(const float4*)&As[k][ty * 8];
            float4 a1 = *(const float4*)&As[k][ty * 8 + 4];
            float4 bv = *(const float4*)&Bs[k][tx * 4];
            float a[8] = {a0.x, a0.y, a0.z, a0.w, a1.x, a1.y, a1.z, a1.w};
            #pragma unroll
            for (int i = 0; i < 8; i++) {
                acc[i].x += a[i] * bv.x;
                acc[i].y += a[i] * bv.y;
                acc[i].z += a[i] * bv.z;
                acc[i].w += a[i] * bv.w;
            }
        }
        __syncthreads();
    }
    #pragma unroll
    for (int i = 0; i < 8; i++) {
        int row = m0 + ty * 8 + i;
        if (row < M)
            *(float4*)(C + (size_t)row * Nn + n0 + tx * 4) = acc[i];
    }
}

// ---------------- attention logits ----------------------------------------
// layer 1: warp per node, lane owns 8 channels (one head per 8 lanes)
__global__ void al1_kernel(const float* __restrict__ asrc,
                           const float* __restrict__ adst, int N) {
    int gw = (blockIdx.x * blockDim.x + threadIdx.x) >> 5;
    int lane = threadIdx.x & 31;
    if (gw >= N) return;
    size_t base = (size_t)gw * 256 + lane * 8;
    float4 h0 = *(const float4*)&g_h1[base];
    float4 h1v = *(const float4*)&g_h1[base + 4];
    float4 s0 = *(const float4*)&asrc[lane * 8];
    float4 s1 = *(const float4*)&asrc[lane * 8 + 4];
    float4 d0 = *(const float4*)&adst[lane * 8];
    float4 d1 = *(const float4*)&adst[lane * 8 + 4];
    float ps = h0.x * s0.x + h0.y * s0.y + h0.z * s0.z + h0.w * s0.w
             + h1v.x * s1.x + h1v.y * s1.y + h1v.z * s1.z + h1v.w * s1.w;
    float pd = h0.x * d0.x + h0.y * d0.y + h0.z * d0.z + h0.w * d0.w
             + h1v.x * d1.x + h1v.y * d1.y + h1v.z * d1.z + h1v.w * d1.w;
    #pragma unroll
    for (int o = 4; o; o >>= 1) {
        ps += __shfl_xor_sync(0xffffffffu, ps, o);
        pd += __shfl_xor_sync(0xffffffffu, pd, o);
    }
    if ((lane & 7) == 0) {
        g_als1[gw * 4 + (lane >> 3)] = ps;
        g_ald1[gw * 4 + (lane >> 3)] = pd;
    }
}

// layer 2 (single head, C=64): warp per node, lane owns 2 channels
__global__ void al2_kernel(const float* __restrict__ asrc,
                           const float* __restrict__ adst, int N) {
    int gw = (blockIdx.x * blockDim.x + threadIdx.x) >> 5;
    int lane = threadIdx.x & 31;
    if (gw >= N) return;
    float2 h = *(const float2*)&g_h2[(size_t)gw * 64 + lane * 2];
    float2 sv = *(const float2*)&asrc[lane * 2];
    float2 dv = *(const float2*)&adst[lane * 2];
    float ps = h.x * sv.x + h.y * sv.y;
    float pd = h.x * dv.x + h.y * dv.y;
    ps = wredsum(ps);
    pd = wredsum(pd);
    if (lane == 0) { g_als2[gw] = ps; g_ald2[gw] = pd; }
}

// ---------------- GAT softmax + aggregation, layer 1 (H=4, C=64) ----------
// warp per destination node; lane owns channels [lane*8, lane*8+8)
__global__ __launch_bounds__(256) void aggregate1_kernel(int N) {
    int d = (blockIdx.x * blockDim.x + threadIdx.x) >> 5;
    int lane = threadIdx.x & 31;
    if (d >= N) return;
    int beg = g_rowoff[d], end = g_rowoff[d + 1];
    float4 ad = *(const float4*)&g_ald1[d * 4];

    // phase 1: per-head max over incoming edges (lane-strided)
    float4 m = make_float4(-1e30f, -1e30f, -1e30f, -1e30f);
    for (int i = beg + lane; i < end; i += 32) {
        int s = g_csr[i];
        float4 as = *(const float4*)&g_als1[s * 4];
        m.x = fmaxf(m.x, lrelu(as.x + ad.x));
        m.y = fmaxf(m.y, lrelu(as.y + ad.y));
        m.z = fmaxf(m.z, lrelu(as.z + ad.z));
        m.w = fmaxf(m.w, lrelu(as.w + ad.w));
    }
    m.x = wredmax(m.x); m.y = wredmax(m.y); m.z = wredmax(m.z); m.w = wredmax(m.w);

    // phase 2: per-head denominator
    float4 den = make_float4(0.f, 0.f, 0.f, 0.f);
    for (int i = beg + lane; i < end; i += 32) {
        int s = g_csr[i];
        float4 as = *(const float4*)&g_als1[s * 4];
        den.x += __expf(lrelu(as.x + ad.x) - m.x);
        den.y += __expf(lrelu(as.y + ad.y) - m.y);
        den.z += __expf(lrelu(as.z + ad.z) - m.z);
        den.w += __expf(lrelu(as.w + ad.w) - m.w);
    }
    den.x = wredsum(den.x); den.y = wredsum(den.y);
    den.z = wredsum(den.z); den.w = wredsum(den.w);
    float4 inv = make_float4(1.f / den.x, 1.f / den.y, 1.f / den.z, 1.f / den.w);

    // phase 3: chunked aggregation (8 edges/chunk; lane j*4+h owns w[edge j][head h])
    int hsel = lane >> 3;                  // head of this lane's channel group
    int j = lane >> 2, hh = lane & 3;      // (edge-in-chunk, head) for weight calc
    float adh = (hh == 0) ? ad.x : (hh == 1) ? ad.y : (hh == 2) ? ad.z : ad.w;
    float mhh = (hh == 0) ? m.x : (hh == 1) ? m.y : (hh == 2) ? m.z : m.w;
    float ivh = (hh == 0) ? inv.x : (hh == 1) ? inv.y : (hh == 2) ? inv.z : inv.w;

    float acc[8];
    #pragma unroll
    for (int i = 0; i < 8; i++) acc[i] = 0.f;

    for (int b0 = beg; b0 < end; b0 += 8) {
        int nE = min(8, end - b0);
        float w = 0.f;
        int sj = 0;
        if (j < nE) {
            sj = g_csr[b0 + j];
            float v = lrelu(g_als1[sj * 4 + hh] + adh);
            w = __expf(v - mhh) * ivh;
        }
        for (int jj = 0; jj < nE; jj++) {
            int s = __shfl_sync(0xffffffffu, sj, jj * 4);
            float wgt = __shfl_sync(0xffffffffu, w, jj * 4 + hsel);
            const float4* hp = (const float4*)(g_h1 + (size_t)s * 256 + lane * 8);
            float4 p0 = hp[0];
            float4 p1 = hp[1];
            acc[0] += wgt * p0.x; acc[1] += wgt * p0.y;
            acc[2] += wgt * p0.z; acc[3] += wgt * p0.w;
            acc[4] += wgt * p1.x; acc[5] += wgt * p1.y;
            acc[6] += wgt * p1.z; acc[7] += wgt * p1.w;
        }
    }
    size_t base = (size_t)d * 256 + lane * 8;
    *(float4*)&g_agg1[base]     = make_float4(acc[0], acc[1], acc[2], acc[3]);
    *(float4*)&g_agg1[base + 4] = make_float4(acc[4], acc[5], acc[6], acc[7]);
}

// ---------------- GAT softmax + aggregation, layer 2 (H=1, C=64) ----------
__global__ __launch_bounds__(256) void aggregate2_kernel(int N) {
    int d = (blockIdx.x * blockDim.x + threadIdx.x) >> 5;
    int lane = threadIdx.x & 31;
    if (d >= N) return;
    int beg = g_rowoff[d], end = g_rowoff[d + 1];
    float adv = g_ald2[d];

    float m = -1e30f;
    for (int i = beg + lane; i < end; i += 32)
        m = fmaxf(m, lrelu(g_als2[g_csr[i]] + adv));
    m = wredmax(m);

    float den = 0.f;
    for (int i = beg + lane; i < end; i += 32)
        den += __expf(lrelu(g_als2[g_csr[i]] + adv) - m);
    den = wredsum(den);
    float inv = 1.f / den;

    float acc0 = 0.f, acc1 = 0.f;
    for (int b0 = beg; b0 < end; b0 += 32) {
        int nE = min(32, end - b0);
        float w = 0.f;
        int sj = 0;
        if (lane < nE) {
            sj = g_csr[b0 + lane];
            w = __expf(lrelu(g_als2[sj] + adv) - m) * inv;
        }
        for (int jj = 0; jj < nE; jj++) {
            int s = __shfl_sync(0xffffffffu, sj, jj);
            float wg = __shfl_sync(0xffffffffu, w, jj);
            float2 p = *(const float2*)&g_h2[(size_t)s * 64 + lane * 2];
            acc0 += wg * p.x;
            acc1 += wg * p.y;
        }
    }
    *(float2*)&g_agg2[(size_t)d * 64 + lane * 2] = make_float2(acc0, acc1);
}

// ---------------- bias + LayerNorm + ReLU (in place) -----------------------
__global__ void post1_kernel(const float* __restrict__ b1,
                             const float* __restrict__ g,
                             const float* __restrict__ bb, int N) {
    int gw = (blockIdx.x * blockDim.x + threadIdx.x) >> 5;
    int lane = threadIdx.x & 31;
    if (gw >= N) return;
    size_t base = (size_t)gw * 256 + lane * 8;
    float4 x0 = *(const float4*)&g_agg1[base];
    float4 x1 = *(const float4*)&g_agg1[base + 4];
    float4 bv0 = *(const float4*)&b1[lane * 8];
    float4 bv1 = *(const float4*)&b1[lane * 8 + 4];
    x0.x += bv0.x; x0.y += bv0.y; x0.z += bv0.z; x0.w += bv0.w;
    x1.x += bv1.x; x1.y += bv1.y; x1.z += bv1.z; x1.w += bv1.w;
    float s = x0.x + x0.y + x0.z + x0.w + x1.x + x1.y + x1.z + x1.w;
    float q = x0.x * x0.x + x0.y * x0.y + x0.z * x0.z + x0.w * x0.w
            + x1.x * x1.x + x1.y * x1.y + x1.z * x1.z + x1.w * x1.w;
    s = wredsum(s);
    q = wredsum(q);
    float mu = s * (1.f / 256.f);
    float var = q * (1.f / 256.f) - mu * mu;
    float rs = rsqrtf(var + LN_EPS);
    float4 g0 = *(const float4*)&g[lane * 8];
    float4 g1 = *(const float4*)&g[lane * 8 + 4];
    float4 q0 = *(const float4*)&bb[lane * 8];
    float4 q1 = *(const float4*)&bb[lane * 8 + 4];
    float4 y0, y1;
    y0.x = fmaxf((x0.x - mu) * rs * g0.x + q0.x, 0.f);
    y0.y = fmaxf((x0.y - mu) * rs * g0.y + q0.y, 0.f);
    y0.z = fmaxf((x0.z - mu) * rs * g0.z + q0.z, 0.f);
    y0.w = fmaxf((x0.w - mu) * rs * g0.w + q0.w, 0.f);
    y1.x = fmaxf((x1.x - mu) * rs * g1.x + q1.x, 0.f);
    y1.y = fmaxf((x1.y - mu) * rs * g1.y + q1.y, 0.f);
    y1.z = fmaxf((x1.z - mu) * rs * g1.z + q1.z, 0.f);
    y1.w = fmaxf((x1.w - mu) * rs * g1.w + q1.w, 0.f);
    *(float4*)&g_agg1[base]     = y0;
    *(float4*)&g_agg1[base + 4] = y1;
}

__global__ void post2_kernel(const float* __restrict__ b2,
                             const float* __restrict__ g,
                             const float* __restrict__ bb, int N) {
    int gw = (blockIdx.x * blockDim.x + threadIdx.x) >> 5;
    int lane = threadIdx.x & 31;
    if (gw >= N) return;
    size_t base = (size_t)gw * 64 + lane * 2;
    float2 x = *(const float2*)&g_agg2[base];
    float2 bv = *(const float2*)&b2[lane * 2];
    x.x += bv.x; x.y += bv.y;
    float s = wredsum(x.x + x.y);
    float q = wredsum(x.x * x.x + x.y * x.y);
    float mu = s * (1.f / 64.f);
    float var = q * (1.f / 64.f) - mu * mu;
    float rs = rsqrtf(var + LN_EPS);
    float2 gv = *(const float2*)&g[lane * 2];
    float2 qv = *(const float2*)&bb[lane * 2];
    float2 y;
    y.x = fmaxf((x.x - mu) * rs * gv.x + qv.x, 0.f);
    y.y = fmaxf((x.y - mu) * rs * gv.y + qv.y, 0.f);
    *(float2*)&g_agg2[base] = y;
}

// ---------------- fused MLP head: 64 -> relu(32) -> 1 ----------------------
__global__ void mlp_kernel(const float* __restrict__ fc1W,
                           const float* __restrict__ fc1b,
                           const float* __restrict__ fc2W,
                           const float* __restrict__ fc2b,
                           float* __restrict__ out, int N) {
    __shared__ float hs[8][64];
    int warp = threadIdx.x >> 5, lane = threadIdx.x & 31;
    int n = blockIdx.x * 8 + warp;
    if (n >= N) return;
    float2 v = *(const float2*)&g_agg2[(size_t)n * 64 + lane * 2];
    hs[warp][lane * 2] = v.x;
    hs[warp][lane * 2 + 1] = v.y;
    __syncwarp();
    float acc = fc1b[lane];
    #pragma unroll
    for (int k = 0; k < 64; k++) acc += hs[warp][k] * fc1W[k * 32 + lane];
    acc = fmaxf(acc, 0.f);
    float o = acc * fc2W[lane];
    o = wredsum(o);
    if (lane == 0) out[n] = o + fc2b[0];
}

// ---------------- launch --------------------------------------------------
extern "C" void kernel_launch(void* const* d_in, const int* in_sizes, int n_in,
                              void* d_out, int out_size) {
    const float* x        = (const float*)d_in[0];
    const int*   ei32     = (const int*)d_in[1];   // int64-or-int32, detected on device
    const float* W1       = (const float*)d_in[2];
    const float* att_src1 = (const float*)d_in[3];
    const float* att_dst1 = (const float*)d_in[4];
    const float* b1       = (const float*)d_in[5];
    const float* ln1_g    = (const float*)d_in[6];
    const float* ln1_b    = (const float*)d_in[7];
    const float* W2       = (const float*)d_in[8];
    const float* att_src2 = (const float*)d_in[9];
    const float* att_dst2 = (const float*)d_in[10];
    const float* b2       = (const float*)d_in[11];
    const float* ln2_g    = (const float*)d_in[12];
    const float* ln2_b    = (const float*)d_in[13];
    const float* fc1_W    = (const float*)d_in[14];
    const float* fc1_b    = (const float*)d_in[15];
    const float* fc2_W    = (const float*)d_in[16];
    const float* fc2_b    = (const float*)d_in[17];
    float* out = (float*)d_out;

    int N = in_sizes[0] / 128;
    int E = in_sizes[1] / 2;
    int ET = E + N;

    // scratch pointers (device globals)
    int* p_count;
    float *p_h1, *p_agg1, *p_h2;
    cudaGetSymbolAddress((void**)&p_count, g_count);
    cudaGetSymbolAddress((void**)&p_h1, g_h1);
    cudaGetSymbolAddress((void**)&p_agg1, g_agg1);
    cudaGetSymbolAddress((void**)&p_h2, g_h2);

    int nwblk = (N + 7) / 8;  // warp-per-node kernels, 256 thr = 8 warps

    // --- graph prep: histogram -> scan -> scatter (CSR by dst) ---
    zero_int_kernel<<<(N + 255) / 256, 256>>>(p_count, N);
    prep_edges_kernel<<<(ET + 255) / 256, 256>>>(ei32, E, N);
    scan_kernel<<<1, 1024>>>(N, ET);
    scatter_kernel<<<(ET + 255) / 256, 256>>>(ET);

    // --- layer 1 ---
    {
        dim3 grid((N + 127) / 128, 256 / 64);
        sgemm_128x64_kernel<<<grid, 256>>>(x, W1, p_h1, N, 128, 256);
    }
    al1_kernel<<<nwblk, 256>>>(att_src1, att_dst1, N);
    aggregate1_kernel<<<nwblk, 256>>>(N);
    post1_kernel<<<nwblk, 256>>>(b1, ln1_g, ln1_b, N);

    // --- layer 2 ---
    {
        dim3 grid((N + 127) / 128, 1);
        sgemm_128x64_kernel<<<grid, 256>>>(p_agg1, W2, p_h2, N, 256, 64);
    }
    al2_kernel<<<nwblk, 256>>>(att_src2, att_dst2, N);
    aggregate2_kernel<<<nwblk, 256>>>(N);
    post2_kernel<<<nwblk, 256>>>(b2, ln2_g, ln2_b, N);

    // --- MLP head ---
    mlp_kernel<<<nwblk, 256>>>(fc1_W, fc1_b, fc2_W, fc2_b, out, N);
}

// round 16
// speedup vs baseline: 1.3034x; 1.3034x over previous
#include <cuda_runtime.h>

// ---------------- problem-size constants (fixed by the dataset) ----------
#define MAXN 50000
#define MAXE 800000
#define MAXET (MAXN + MAXE)

// ---------------- scratch (device globals; no allocation allowed) --------
__device__ int   g_src[MAXET];
__device__ int   g_dst[MAXET];
__device__ int   g_csr[MAXET];
__device__ int   g_count[MAXN];
__device__ int   g_rowoff[MAXN + 1];
__device__ int   g_cursor[MAXN];
__device__ float g_h1[(size_t)MAXN * 256];
__device__ float g_agg1[(size_t)MAXN * 256];
__device__ float g_als1[MAXN * 4];
__device__ float g_ald1[MAXN * 4];
__device__ float g_h2[(size_t)MAXN * 64];
__device__ float g_als2[MAXN];
__device__ float g_ald2[MAXN];

#define NEG_SLOPE 0.2f
#define LN_EPS 1e-5f

// ---------------- helpers -------------------------------------------------
__device__ __forceinline__ float lrelu(float v) { return v > 0.f ? v : NEG_SLOPE * v; }
__device__ __forceinline__ float wredmax(float v) {
    #pragma unroll
    for (int o = 16; o; o >>= 1) v = fmaxf(v, __shfl_xor_sync(0xffffffffu, v, o));
    return v;
}
__device__ __forceinline__ float wredsum(float v) {
    #pragma unroll
    for (int o = 16; o; o >>= 1) v += __shfl_xor_sync(0xffffffffu, v, o);
    return v;
}
__device__ __forceinline__ unsigned f2tf(float x) {
    unsigned u;
    asm("cvt.rna.tf32.f32 %0, %1;" : "=r"(u) : "f"(x));
    return u;
}

// ---------------- graph prep ----------------------------------------------
__global__ void zero_int_kernel(int* __restrict__ p, int n) {
    int i = blockIdx.x * blockDim.x + threadIdx.x;
    if (i < n) p[i] = 0;
}

// edge_index may be int64 (values < 2^31, high words 0) or int32.
__global__ void prep_edges_kernel(const int* __restrict__ ei32, int E, int N) {
    int i = blockIdx.x * blockDim.x + threadIdx.x;
    int ET = E + N;
    if (i >= ET) return;
    bool is64 = true;
    #pragma unroll
    for (int t = 1; t <= 31; t += 2) is64 = is64 && (ei32[t] == 0);
    int s, d;
    if (i < E) {
        if (is64) { s = ei32[2 * i];     d = ei32[2 * (E + i)]; }
        else      { s = ei32[i];         d = ei32[E + i]; }
    } else {
        s = d = i - E;  // self-loops appended (PyG add_self_loops)
    }
    g_src[i] = s;
    g_dst[i] = d;
    atomicAdd(&g_count[d], 1);
}

// single-block exclusive scan of counts -> rowoff + cursor copy
__global__ void scan_kernel(int N, int ET) {
    __shared__ int s[1024];
    int t = threadIdx.x;
    int chunk = (N + 1023) / 1024;
    int b = t * chunk;
    int e = min(N, b + chunk);
    int sum = 0;
    for (int i = b; i < e; i++) sum += g_count[i];
    s[t] = sum;
    __syncthreads();
    for (int o = 1; o < 1024; o <<= 1) {
        int v = (t >= o) ? s[t - o] : 0;
        __syncthreads();
        s[t] += v;
        __syncthreads();
    }
    int run = (t > 0) ? s[t - 1] : 0;
    for (int i = b; i < e; i++) {
        g_rowoff[i] = run;
        g_cursor[i] = run;
        run += g_count[i];
    }
    if (t == 1023) g_rowoff[N] = s[1023];
}

__global__ void scatter_kernel(int ET) {
    int i = blockIdx.x * blockDim.x + threadIdx.x;
    if (i >= ET) return;
    int d = g_dst[i];
    int pos = atomicAdd(&g_cursor[d], 1);
    g_csr[pos] = g_src[i];
}

// ---------------- TF32 tensor-core GEMM: C[M,Nn] = A[M,K] @ B[K,Nn] -------
// Block tile 128x64, BK=32. 8 warps (4x2), warp tile 32x32 via m16n8k8 mma.
__global__ __launch_bounds__(256) void gemm_tf32_kernel(
    const float* __restrict__ A, const float* __restrict__ B,
    float* __restrict__ C, int M, int K, int Nn) {
    __shared__ unsigned As[128][36];  // [m][k], pad 36 -> conflict-free frag loads
    __shared__ unsigned Bs[32][72];   // [k][n], pad 72

    int tid = threadIdx.x;
    int warp = tid >> 5, lane = tid & 31;
    int gid = lane >> 2, tcol = lane & 3;
    int wm = warp & 3, wn = warp >> 2;
    int m0 = blockIdx.x * 128, n0 = blockIdx.y * 64;

    float acc[2][4][4];
    #pragma unroll
    for (int im = 0; im < 2; im++)
        #pragma unroll
        for (int jn = 0; jn < 4; jn++)
            #pragma unroll
            for (int q = 0; q < 4; q++) acc[im][jn][q] = 0.f;

    for (int k0 = 0; k0 < K; k0 += 32) {
        // A tile: 128x32 floats = 1024 float4, 4 per thread
        #pragma unroll
        for (int r = 0; r < 4; r++) {
            int f = tid + r * 256;
            int row = f >> 3, kq = f & 7;
            float4 v = make_float4(0.f, 0.f, 0.f, 0.f);
            if (m0 + row < M)
                v = *(const float4*)(A + (size_t)(m0 + row) * K + k0 + kq * 4);
            uint4 u = make_uint4(f2tf(v.x), f2tf(v.y), f2tf(v.z), f2tf(v.w));
            *(uint4*)&As[row][kq * 4] = u;
        }
        // B tile: 32x64 floats = 512 float4, 2 per thread
        #pragma unroll
        for (int r = 0; r < 2; r++) {
            int f = tid + r * 256;
            int kr = f >> 4, nq = f & 15;
            float4 v = *(const float4*)(B + (size_t)(k0 + kr) * Nn + n0 + nq * 4);
            uint4 u = make_uint4(f2tf(v.x), f2tf(v.y), f2tf(v.z), f2tf(v.w));
            *(uint4*)&Bs[kr][nq * 4] = u;
        }
        __syncthreads();
        #pragma unroll
        for (int ks = 0; ks < 4; ks++) {
            int kb = ks * 8;
            unsigned a[2][4], b[4][2];
            #pragma unroll
            for (int im = 0; im < 2; im++) {
                int mrow = wm * 32 + im * 16 + gid;
                a[im][0] = As[mrow][kb + tcol];
                a[im][1] = As[mrow + 8][kb + tcol];
                a[im][2] = As[mrow][kb + tcol + 4];
                a[im][3] = As[mrow + 8][kb + tcol + 4];
            }
            #pragma unroll
            for (int jn = 0; jn < 4; jn++) {
                int nc = wn * 32 + jn * 8 + gid;
                b[jn][0] = Bs[kb + tcol][nc];
                b[jn][1] = Bs[kb + tcol + 4][nc];
            }
            #pragma unroll
            for (int im = 0; im < 2; im++)
                #pragma unroll
                for (int jn = 0; jn < 4; jn++)
                    asm volatile(
                        "mma.sync.aligned.m16n8k8.row.col.f32.tf32.tf32.f32 "
                        "{%0,%1,%2,%3}, {%4,%5,%6,%7}, {%8,%9}, {%0,%1,%2,%3};"
                        : "+f"(acc[im][jn][0]), "+f"(acc[im][jn][1]),
                          "+f"(acc[im][jn][2]), "+f"(acc[im][jn][3])
                        : "r"(a[im][0]), "r"(a[im][1]), "r"(a[im][2]), "r"(a[im][3]),
                          "r"(b[jn][0]), "r"(b[jn][1]));
        }
        __syncthreads();
    }
    // epilogue: c0/c1 -> (row, 2*tcol..+1), c2/c3 -> (row+8, ...)
    #pragma unroll
    for (int im = 0; im < 2; im++) {
        int r = m0 + wm * 32 + im * 16 + gid;
        #pragma unroll
        for (int jn = 0; jn < 4; jn++) {
            int col = n0 + wn * 32 + jn * 8 + 2 * tcol;
            if (r < M)
                *(float2*)(C + (size_t)r * Nn + col) =
                    make_float2(acc[im][jn][0], acc[im][jn][1]);
            if (r + 8 < M)
                *(float2*)(C + (size_t)(r + 8) * Nn + col) =
                    make_float2(acc[im][jn][2], acc[im][jn][3]);
        }
    }
}

// ---------------- attention logits ----------------------------------------
// layer 1: warp per node, lane owns 8 channels (one head per 8 lanes)
__global__ void al1_kernel(const float* __restrict__ asrc,
                           const float* __restrict__ adst, int N) {
    int gw = (blockIdx.x * blockDim.x + threadIdx.x) >> 5;
    int lane = threadIdx.x & 31;
    if (gw >= N) return;
    size_t base = (size_t)gw * 256 + lane * 8;
    float4 h0 = *(const float4*)&g_h1[base];
    float4 h1v = *(const float4*)&g_h1[base + 4];
    float4 s0 = *(const float4*)&asrc[lane * 8];
    float4 s1 = *(const float4*)&asrc[lane * 8 + 4];
    float4 d0 = *(const float4*)&adst[lane * 8];
    float4 d1 = *(const float4*)&adst[lane * 8 + 4];
    float ps = h0.x * s0.x + h0.y * s0.y + h0.z * s0.z + h0.w * s0.w
             + h1v.x * s1.x + h1v.y * s1.y + h1v.z * s1.z + h1v.w * s1.w;
    float pd = h0.x * d0.x + h0.y * d0.y + h0.z * d0.z + h0.w * d0.w
             + h1v.x * d1.x + h1v.y * d1.y + h1v.z * d1.z + h1v.w * d1.w;
    #pragma unroll
    for (int o = 4; o; o >>= 1) {
        ps += __shfl_xor_sync(0xffffffffu, ps, o);
        pd += __shfl_xor_sync(0xffffffffu, pd, o);
    }
    if ((lane & 7) == 0) {
        g_als1[gw * 4 + (lane >> 3)] = ps;
        g_ald1[gw * 4 + (lane >> 3)] = pd;
    }
}

// layer 2 (single head, C=64): warp per node, lane owns 2 channels
__global__ void al2_kernel(const float* __restrict__ asrc,
                           const float* __restrict__ adst, int N) {
    int gw = (blockIdx.x * blockDim.x + threadIdx.x) >> 5;
    int lane = threadIdx.x & 31;
    if (gw >= N) return;
    float2 h = *(const float2*)&g_h2[(size_t)gw * 64 + lane * 2];
    float2 sv = *(const float2*)&asrc[lane * 2];
    float2 dv = *(const float2*)&adst[lane * 2];
    float ps = h.x * sv.x + h.y * sv.y;
    float pd = h.x * dv.x + h.y * dv.y;
    ps = wredsum(ps);
    pd = wredsum(pd);
    if (lane == 0) { g_als2[gw] = ps; g_ald2[gw] = pd; }
}

// ---------------- GAT softmax + aggregation + bias + LN + ReLU, layer 1 ----
// warp per destination node; lane owns channels [lane*8, lane*8+8)
__global__ __launch_bounds__(256) void aggregate1_kernel(
    const float* __restrict__ b1, const float* __restrict__ lng,
    const float* __restrict__ lnb, int N) {
    int d = (blockIdx.x * blockDim.x + threadIdx.x) >> 5;
    int lane = threadIdx.x & 31;
    if (d >= N) return;
    int beg = g_rowoff[d], end = g_rowoff[d + 1];
    float4 ad = *(const float4*)&g_ald1[d * 4];

    // phase 1: per-head max over incoming edges (lane-strided)
    float4 m = make_float4(-1e30f, -1e30f, -1e30f, -1e30f);
    for (int i = beg + lane; i < end; i += 32) {
        int s = g_csr[i];
        float4 as = *(const float4*)&g_als1[s * 4];
        m.x = fmaxf(m.x, lrelu(as.x + ad.x));
        m.y = fmaxf(m.y, lrelu(as.y + ad.y));
        m.z = fmaxf(m.z, lrelu(as.z + ad.z));
        m.w = fmaxf(m.w, lrelu(as.w + ad.w));
    }
    m.x = wredmax(m.x); m.y = wredmax(m.y); m.z = wredmax(m.z); m.w = wredmax(m.w);

    // phase 2: per-head denominator
    float4 den = make_float4(0.f, 0.f, 0.f, 0.f);
    for (int i = beg + lane; i < end; i += 32) {
        int s = g_csr[i];
        float4 as = *(const float4*)&g_als1[s * 4];
        den.x += __expf(lrelu(as.x + ad.x) - m.x);
        den.y += __expf(lrelu(as.y + ad.y) - m.y);
        den.z += __expf(lrelu(as.z + ad.z) - m.z);
        den.w += __expf(lrelu(as.w + ad.w) - m.w);
    }
    den.x = wredsum(den.x); den.y = wredsum(den.y);
    den.z = wredsum(den.z); den.w = wredsum(den.w);
    float4 inv = make_float4(1.f / den.x, 1.f / den.y, 1.f / den.z, 1.f / den.w);

    // phase 3: chunked aggregation (8 edges/chunk; lane j*4+h owns w[edge j][head h])
    int hsel = lane >> 3;                  // head of this lane's channel group
    int j = lane >> 2, hh = lane & 3;      // (edge-in-chunk, head) for weight calc
    float adh = (hh == 0) ? ad.x : (hh == 1) ? ad.y : (hh == 2) ? ad.z : ad.w;
    float mhh = (hh == 0) ? m.x : (hh == 1) ? m.y : (hh == 2) ? m.z : m.w;
    float ivh = (hh == 0) ? inv.x : (hh == 1) ? inv.y : (hh == 2) ? inv.z : inv.w;

    float acc[8];
    #pragma unroll
    for (int i = 0; i < 8; i++) acc[i] = 0.f;

    for (int b0 = beg; b0 < end; b0 += 8) {
        int nE = min(8, end - b0);
        float w = 0.f;
        int sj = 0;
        if (j < nE) {
            sj = g_csr[b0 + j];
            float v = lrelu(g_als1[sj * 4 + hh] + adh);
            w = __expf(v - mhh) * ivh;
        }
        for (int jj = 0; jj < nE; jj++) {
            int s = __shfl_sync(0xffffffffu, sj, jj * 4);
            float wgt = __shfl_sync(0xffffffffu, w, jj * 4 + hsel);
            const float4* hp = (const float4*)(g_h1 + (size_t)s * 256 + lane * 8);
            float4 p0 = hp[0];
            float4 p1 = hp[1];
            acc[0] += wgt * p0.x; acc[1] += wgt * p0.y;
            acc[2] += wgt * p0.z; acc[3] += wgt * p0.w;
            acc[4] += wgt * p1.x; acc[5] += wgt * p1.y;
            acc[6] += wgt * p1.z; acc[7] += wgt * p1.w;
        }
    }

    // fused: bias + LayerNorm(256) + ReLU, then single write
    float4 bv0 = *(const float4*)&b1[lane * 8];
    float4 bv1 = *(const float4*)&b1[lane * 8 + 4];
    acc[0] += bv0.x; acc[1] += bv0.y; acc[2] += bv0.z; acc[3] += bv0.w;
    acc[4] += bv1.x; acc[5] += bv1.y; acc[6] += bv1.z; acc[7] += bv1.w;
    float s = 0.f, q = 0.f;
    #pragma unroll
    for (int i = 0; i < 8; i++) { s += acc[i]; q += acc[i] * acc[i]; }
    s = wredsum(s);
    q = wredsum(q);
    float mu = s * (1.f / 256.f);
    float var = q * (1.f / 256.f) - mu * mu;
    float rs = rsqrtf(var + LN_EPS);
    float4 g0 = *(const float4*)&lng[lane * 8];
    float4 g1 = *(const float4*)&lng[lane * 8 + 4];
    float4 q0 = *(const float4*)&lnb[lane * 8];
    float4 q1 = *(const float4*)&lnb[lane * 8 + 4];
    float gg[8] = {g0.x, g0.y, g0.z, g0.w, g1.x, g1.y, g1.z, g1.w};
    float qq[8] = {q0.x, q0.y, q0.z, q0.w, q1.x, q1.y, q1.z, q1.w};
    float y[8];
    #pragma unroll
    for (int i = 0; i < 8; i++)
        y[i] = fmaxf((acc[i] - mu) * rs * gg[i] + qq[i], 0.f);
    size_t base = (size_t)d * 256 + lane * 8;
    *(float4*)&g_agg1[base]     = make_float4(y[0], y[1], y[2], y[3]);
    *(float4*)&g_agg1[base + 4] = make_float4(y[4], y[5], y[6], y[7]);
}

// ------ GAT layer 2 (H=1, C=64) + bias + LN + ReLU + fused MLP head --------
__global__ __launch_bounds__(256) void aggregate2_kernel(
    const float* __restrict__ b2, const float* __restrict__ lng,
    const float* __restrict__ lnb,
    const float* __restrict__ fc1W, const float* __restrict__ fc1b,
    const float* __restrict__ fc2W, const float* __restrict__ fc2b,
    float* __restrict__ out, int N) {
    __shared__ float hs[8][64];
    int warp = threadIdx.x >> 5, lane = threadIdx.x & 31;
    int d = blockIdx.x * 8 + warp;
    if (d >= N) return;
    int beg = g_rowoff[d], end = g_rowoff[d + 1];
    float adv = g_ald2[d];

    float m = -1e30f;
    for (int i = beg + lane; i < end; i += 32)
        m = fmaxf(m, lrelu(g_als2[g_csr[i]] + adv));
    m = wredmax(m);

    float den = 0.f;
    for (int i = beg + lane; i < end; i += 32)
        den += __expf(lrelu(g_als2[g_csr[i]] + adv) - m);
    den = wredsum(den);
    float inv = 1.f / den;

    float acc0 = 0.f, acc1 = 0.f;
    for (int b0 = beg; b0 < end; b0 += 32) {
        int nE = min(32, end - b0);
        float w = 0.f;
        int sj = 0;
        if (lane < nE) {
            sj = g_csr[b0 + lane];
            w = __expf(lrelu(g_als2[sj] + adv) - m) * inv;
        }
        for (int jj = 0; jj < nE; jj++) {
            int s = __shfl_sync(0xffffffffu, sj, jj);
            float wg = __shfl_sync(0xffffffffu, w, jj);
            float2 p = *(const float2*)&g_h2[(size_t)s * 64 + lane * 2];
            acc0 += wg * p.x;
            acc1 += wg * p.y;
        }
    }

    // fused: bias + LayerNorm(64) + ReLU
    float2 bv = *(const float2*)&b2[lane * 2];
    acc0 += bv.x; acc1 += bv.y;
    float s = wredsum(acc0 + acc1);
    float q = wredsum(acc0 * acc0 + acc1 * acc1);
    float mu = s * (1.f / 64.f);
    float var = q * (1.f / 64.f) - mu * mu;
    float rs = rsqrtf(var + LN_EPS);
    float2 gv = *(const float2*)&lng[lane * 2];
    float2 qv = *(const float2*)&lnb[lane * 2];
    float y0 = fmaxf((acc0 - mu) * rs * gv.x + qv.x, 0.f);
    float y1 = fmaxf((acc1 - mu) * rs * gv.y + qv.y, 0.f);

    // fused MLP head: 64 -> relu(32) -> 1
    hs[warp][lane * 2] = y0;
    hs[warp][lane * 2 + 1] = y1;
    __syncwarp();
    float a = fc1b[lane];
    #pragma unroll
    for (int k = 0; k < 64; k++) a += hs[warp][k] * fc1W[k * 32 + lane];
    a = fmaxf(a, 0.f);
    float o = wredsum(a * fc2W[lane]);
    if (lane == 0) out[d] = o + fc2b[0];
}

// ---------------- launch --------------------------------------------------
extern "C" void kernel_launch(void* const* d_in, const int* in_sizes, int n_in,
                              void* d_out, int out_size) {
    const float* x        = (const float*)d_in[0];
    const int*   ei32     = (const int*)d_in[1];   // int64-or-int32, detected on device
    const float* W1       = (const float*)d_in[2];
    const float* att_src1 = (const float*)d_in[3];
    const float* att_dst1 = (const float*)d_in[4];
    const float* b1       = (const float*)d_in[5];
    const float* ln1_g    = (const float*)d_in[6];
    const float* ln1_b    = (const float*)d_in[7];
    const float* W2       = (const float*)d_in[8];
    const float* att_src2 = (const float*)d_in[9];
    const float* att_dst2 = (const float*)d_in[10];
    const float* b2       = (const float*)d_in[11];
    const float* ln2_g    = (const float*)d_in[12];
    const float* ln2_b    = (const float*)d_in[13];
    const float* fc1_W    = (const float*)d_in[14];
    const float* fc1_b    = (const float*)d_in[15];
    const float* fc2_W    = (const float*)d_in[16];
    const float* fc2_b    = (const float*)d_in[17];
    float* out = (float*)d_out;

    int N = in_sizes[0] / 128;
    int E = in_sizes[1] / 2;
    int ET = E + N;

    int* p_count;
    float *p_h1, *p_agg1, *p_h2;
    cudaGetSymbolAddress((void**)&p_count, g_count);
    cudaGetSymbolAddress((void**)&p_h1, g_h1);
    cudaGetSymbolAddress((void**)&p_agg1, g_agg1);
    cudaGetSymbolAddress((void**)&p_h2, g_h2);

    int nwblk = (N + 7) / 8;  // warp-per-node kernels, 256 thr = 8 warps

    // --- graph prep: histogram -> scan -> scatter (CSR by dst) ---
    zero_int_kernel<<<(N + 255) / 256, 256>>>(p_count, N);
    prep_edges_kernel<<<(ET + 255) / 256, 256>>>(ei32, E, N);
    scan_kernel<<<1, 1024>>>(N, ET);
    scatter_kernel<<<(ET + 255) / 256, 256>>>(ET);

    // --- layer 1: h1 = x @ W1 (tf32 TC), logits, softmax-agg + LN fused ---
    {
        dim3 grid((N + 127) / 128, 4);
        gemm_tf32_kernel<<<grid, 256>>>(x, W1, p_h1, N, 128, 256);
    }
    al1_kernel<<<nwblk, 256>>>(att_src1, att_dst1, N);
    aggregate1_kernel<<<nwblk, 256>>>(b1, ln1_g, ln1_b, N);

    // --- layer 2: h2 = agg1 @ W2 (tf32 TC), logits, agg + LN + MLP fused ---
    {
        dim3 grid((N + 127) / 128, 1);
        gemm_tf32_kernel<<<grid, 256>>>(p_agg1, W2, p_h2, N, 256, 64);
    }
    al2_kernel<<<nwblk, 256>>>(att_src2, att_dst2, N);
    aggregate2_kernel<<<nwblk, 256>>>(b2, ln2_g, ln2_b,
                                      fc1_W, fc1_b, fc2_W, fc2_b, out, N);
}

// round 17
// speedup vs baseline: 1.4222x; 1.0912x over previous
#include <cuda_runtime.h>

// ---------------- problem-size constants (fixed by the dataset) ----------
#define MAXN 50000
#define MAXE 800000
#define MAXET (MAXN + MAXE)

// ---------------- scratch (device globals; no allocation allowed) --------
__device__ int   g_csr[MAXET];
__device__ int   g_count[MAXN];
__device__ int   g_rowoff[MAXN + 1];
__device__ int   g_cursor[MAXN];
__device__ float g_h1[(size_t)MAXN * 256];
__device__ float g_agg1[(size_t)MAXN * 256];
__device__ float g_als1[MAXN * 4];
__device__ float g_ald1[MAXN * 4];
__device__ float g_h2[(size_t)MAXN * 64];
__device__ float g_als2[MAXN];
__device__ float g_ald2[MAXN];

#define NEG_SLOPE 0.2f
#define LN_EPS 1e-5f

// ---------------- helpers -------------------------------------------------
__device__ __forceinline__ float lrelu(float v) { return v > 0.f ? v : NEG_SLOPE * v; }
__device__ __forceinline__ float wredsum(float v) {
    #pragma unroll
    for (int o = 16; o; o >>= 1) v += __shfl_xor_sync(0xffffffffu, v, o);
    return v;
}
__device__ __forceinline__ unsigned f2tf(float x) {
    unsigned u;
    asm("cvt.rna.tf32.f32 %0, %1;" : "=r"(u) : "f"(x));
    return u;
}

// ---------------- graph prep ----------------------------------------------
__global__ void zero_int_kernel(int* __restrict__ p, int n) {
    int i = blockIdx.x * blockDim.x + threadIdx.x;
    if (i < n) p[i] = 0;
}

// edge_index may be int64 (values < 2^31, high words 0) or int32. Detect by
// checking odd int32 positions: all-zero <=> int64.
__device__ __forceinline__ bool detect_is64(const int* ei32) {
    bool is64 = true;
    #pragma unroll
    for (int t = 1; t <= 31; t += 2) is64 = is64 && (ei32[t] == 0);
    return is64;
}

__global__ void hist_kernel(const int* __restrict__ ei32, int E, int N) {
    int i = blockIdx.x * blockDim.x + threadIdx.x;
    int ET = E + N;
    if (i >= ET) return;
    int d;
    if (i < E) {
        bool is64 = detect_is64(ei32);
        d = is64 ? ei32[2 * (E + i)] : ei32[E + i];
    } else {
        d = i - E;  // self-loops appended (PyG add_self_loops)
    }
    atomicAdd(&g_count[d], 1);
}

// single-block exclusive scan of counts -> rowoff + cursor copy
__global__ void scan_kernel(int N, int ET) {
    __shared__ int s[1024];
    int t = threadIdx.x;
    int chunk = (N + 1023) / 1024;
    int b = t * chunk;
    int e = min(N, b + chunk);
    int sum = 0;
    for (int i = b; i < e; i++) sum += g_count[i];
    s[t] = sum;
    __syncthreads();
    for (int o = 1; o < 1024; o <<= 1) {
        int v = (t >= o) ? s[t - o] : 0;
        __syncthreads();
        s[t] += v;
        __syncthreads();
    }
    int run = (t > 0) ? s[t - 1] : 0;
    for (int i = b; i < e; i++) {
        g_rowoff[i] = run;
        g_cursor[i] = run;
        run += g_count[i];
    }
    if (t == 1023) g_rowoff[N] = s[1023];
}

__global__ void scatter_kernel(const int* __restrict__ ei32, int E, int N) {
    int i = blockIdx.x * blockDim.x + threadIdx.x;
    int ET = E + N;
    if (i >= ET) return;
    int s, d;
    if (i < E) {
        bool is64 = detect_is64(ei32);
        if (is64) { s = ei32[2 * i]; d = ei32[2 * (E + i)]; }
        else      { s = ei32[i];     d = ei32[E + i]; }
    } else {
        s = d = i - E;
    }
    int pos = atomicAdd(&g_cursor[d], 1);
    g_csr[pos] = s;
}

// ------- TF32 tensor-core GEMM + fused attention-logit epilogue -----------
// C[M,Nn] = A[M,K] @ B[K,Nn]; block tile 128x64, BK=32, 8 warps (4x2),
// warp tile 32x32 via m16n8k8. Epilogue also computes, per row r of the
// block's 64-col slice (one attention head):
//   als[r*stride+hidx] = sum_c C[r][n0+c]*asrc[n0+c]   (ald likewise)
__global__ __launch_bounds__(256) void gemm_tf32_fused_kernel(
    const float* __restrict__ A, const float* __restrict__ B,
    float* __restrict__ C,
    const float* __restrict__ asrc, const float* __restrict__ adst,
    float* __restrict__ als, float* __restrict__ ald, int alsStride,
    int M, int K, int Nn) {
    __shared__ unsigned As[128][36];  // [m][k], pad -> conflict-free frag loads
    __shared__ unsigned Bs[32][72];   // [k][n], pad
    __shared__ float s_ps[128][2];
    __shared__ float s_pd[128][2];

    int tid = threadIdx.x;
    int warp = tid >> 5, lane = tid & 31;
    int gid = lane >> 2, tcol = lane & 3;
    int wm = warp & 3, wn = warp >> 2;
    int m0 = blockIdx.x * 128, n0 = blockIdx.y * 64;
    int hidx = blockIdx.y;

    float acc[2][4][4];
    #pragma unroll
    for (int im = 0; im < 2; im++)
        #pragma unroll
        for (int jn = 0; jn < 4; jn++)
            #pragma unroll
            for (int q = 0; q < 4; q++) acc[im][jn][q] = 0.f;

    for (int k0 = 0; k0 < K; k0 += 32) {
        #pragma unroll
        for (int r = 0; r < 4; r++) {
            int f = tid + r * 256;
            int row = f >> 3, kq = f & 7;
            float4 v = make_float4(0.f, 0.f, 0.f, 0.f);
            if (m0 + row < M)
                v = *(const float4*)(A + (size_t)(m0 + row) * K + k0 + kq * 4);
            uint4 u = make_uint4(f2tf(v.x), f2tf(v.y), f2tf(v.z), f2tf(v.w));
            *(uint4*)&As[row][kq * 4] = u;
        }
        #pragma unroll
        for (int r = 0; r < 2; r++) {
            int f = tid + r * 256;
            int kr = f >> 4, nq = f & 15;
            float4 v = *(const float4*)(B + (size_t)(k0 + kr) * Nn + n0 + nq * 4);
            uint4 u = make_uint4(f2tf(v.x), f2tf(v.y), f2tf(v.z), f2tf(v.w));
            *(uint4*)&Bs[kr][nq * 4] = u;
        }
        __syncthreads();
        #pragma unroll
        for (int ks = 0; ks < 4; ks++) {
            int kb = ks * 8;
            unsigned a[2][4], b[4][2];
            #pragma unroll
            for (int im = 0; im < 2; im++) {
                int mrow = wm * 32 + im * 16 + gid;
                a[im][0] = As[mrow][kb + tcol];
                a[im][1] = As[mrow + 8][kb + tcol];
                a[im][2] = As[mrow][kb + tcol + 4];
                a[im][3] = As[mrow + 8][kb + tcol + 4];
            }
            #pragma unroll
            for (int jn = 0; jn < 4; jn++) {
                int nc = wn * 32 + jn * 8 + gid;
                b[jn][0] = Bs[kb + tcol][nc];
                b[jn][1] = Bs[kb + tcol + 4][nc];
            }
            #pragma unroll
            for (int im = 0; im < 2; im++)
                #pragma unroll
                for (int jn = 0; jn < 4; jn++)
                    asm volatile(
                        "mma.sync.aligned.m16n8k8.row.col.f32.tf32.tf32.f32 "
                        "{%0,%1,%2,%3}, {%4,%5,%6,%7}, {%8,%9}, {%0,%1,%2,%3};"
                        : "+f"(acc[im][jn][0]), "+f"(acc[im][jn][1]),
                          "+f"(acc[im][jn][2]), "+f"(acc[im][jn][3])
                        : "r"(a[im][0]), "r"(a[im][1]), "r"(a[im][2]), "r"(a[im][3]),
                          "r"(b[jn][0]), "r"(b[jn][1]));
        }
        __syncthreads();
    }

    // ---- store C ----
    #pragma unroll
    for (int im = 0; im < 2; im++) {
        int r = m0 + wm * 32 + im * 16 + gid;
        #pragma unroll
        for (int jn = 0; jn < 4; jn++) {
            int col = n0 + wn * 32 + jn * 8 + 2 * tcol;
            if (r < M)
                *(float2*)(C + (size_t)r * Nn + col) =
                    make_float2(acc[im][jn][0], acc[im][jn][1]);
            if (r + 8 < M)
                *(float2*)(C + (size_t)(r + 8) * Nn + col) =
                    make_float2(acc[im][jn][2], acc[im][jn][3]);
        }
    }

    // ---- fused attention logits ----
    float ps[2][2] = {{0.f, 0.f}, {0.f, 0.f}};
    float pd[2][2] = {{0.f, 0.f}, {0.f, 0.f}};
    #pragma unroll
    for (int jn = 0; jn < 4; jn++) {
        int c0 = n0 + wn * 32 + jn * 8 + 2 * tcol;
        float as0 = asrc[c0], as1 = asrc[c0 + 1];
        float ad0 = adst[c0], ad1 = adst[c0 + 1];
        #pragma unroll
        for (int im = 0; im < 2; im++) {
            ps[im][0] += acc[im][jn][0] * as0 + acc[im][jn][1] * as1;
            pd[im][0] += acc[im][jn][0] * ad0 + acc[im][jn][1] * ad1;
            ps[im][1] += acc[im][jn][2] * as0 + acc[im][jn][3] * as1;
            pd[im][1] += acc[im][jn][2] * ad0 + acc[im][jn][3] * ad1;
        }
    }
    #pragma unroll
    for (int im = 0; im < 2; im++)
        #pragma unroll
        for (int hf = 0; hf < 2; hf++) {
            #pragma unroll
            for (int o = 1; o <= 2; o <<= 1) {
                ps[im][hf] += __shfl_xor_sync(0xffffffffu, ps[im][hf], o);
                pd[im][hf] += __shfl_xor_sync(0xffffffffu, pd[im][hf], o);
            }
        }
    if (tcol == 0) {
        #pragma unroll
        for (int im = 0; im < 2; im++)
            #pragma unroll
            for (int hf = 0; hf < 2; hf++) {
                int row = wm * 32 + im * 16 + hf * 8 + gid;
                s_ps[row][wn] = ps[im][hf];
                s_pd[row][wn] = pd[im][hf];
            }
    }
    __syncthreads();
    if (tid < 128) {
        int r = m0 + tid;
        if (r < M) {
            als[(size_t)r * alsStride + hidx] = s_ps[tid][0] + s_ps[tid][1];
            ald[(size_t)r * alsStride + hidx] = s_pd[tid][0] + s_pd[tid][1];
        }
    }
}

// -------- GAT layer 1: single-pass softmax-agg + bias + LN + ReLU ---------
// warp per destination node; lane owns channels [lane*8, lane*8+8).
// Unnormalized accumulation: acc = sum_e exp(v_e)*h[src_e], den = sum_e exp(v_e).
__global__ __launch_bounds__(256) void aggregate1_kernel(
    const float* __restrict__ b1, const float* __restrict__ lng,
    const float* __restrict__ lnb, int N) {
    int d = (blockIdx.x * blockDim.x + threadIdx.x) >> 5;
    int lane = threadIdx.x & 31;
    if (d >= N) return;
    int beg = g_rowoff[d], end = g_rowoff[d + 1];
    float4 ad = *(const float4*)&g_ald1[d * 4];

    int hsel = lane >> 3;              // head of this lane's channel group
    int j = lane >> 2, hh = lane & 3;  // (edge-in-chunk, head) for weight calc
    float adh = (hh == 0) ? ad.x : (hh == 1) ? ad.y : (hh == 2) ? ad.z : ad.w;

    float den_loc = 0.f;
    float acc[8];
    #pragma unroll
    for (int i = 0; i < 8; i++) acc[i] = 0.f;

    for (int b0 = beg; b0 < end; b0 += 8) {
        int nE = min(8, end - b0);
        float w = 0.f;
        int sj = 0;
        if (j < nE) {
            sj = g_csr[b0 + j];
            w = __expf(lrelu(g_als1[sj * 4 + hh] + adh));
            den_loc += w;
        }
        for (int jj = 0; jj < nE; jj++) {
            int s = __shfl_sync(0xffffffffu, sj, jj * 4);
            float wgt = __shfl_sync(0xffffffffu, w, jj * 4 + hsel);
            const float4* hp = (const float4*)(g_h1 + (size_t)s * 256 + lane * 8);
            float4 p0 = hp[0];
            float4 p1 = hp[1];
            acc[0] += wgt * p0.x; acc[1] += wgt * p0.y;
            acc[2] += wgt * p0.z; acc[3] += wgt * p0.w;
            acc[4] += wgt * p1.x; acc[5] += wgt * p1.y;
            acc[6] += wgt * p1.z; acc[7] += wgt * p1.w;
        }
    }
    // reduce den over lanes sharing hh (lane bits 2..4), then fetch den[hsel]
    #pragma unroll
    for (int o = 4; o <= 16; o <<= 1)
        den_loc += __shfl_xor_sync(0xffffffffu, den_loc, o);
    float inv = 1.f / __shfl_sync(0xffffffffu, den_loc, hsel);
    #pragma unroll
    for (int i = 0; i < 8; i++) acc[i] *= inv;

    // fused: bias + LayerNorm(256) + ReLU, single write
    float4 bv0 = *(const float4*)&b1[lane * 8];
    float4 bv1 = *(const float4*)&b1[lane * 8 + 4];
    acc[0] += bv0.x; acc[1] += bv0.y; acc[2] += bv0.z; acc[3] += bv0.w;
    acc[4] += bv1.x; acc[5] += bv1.y; acc[6] += bv1.z; acc[7] += bv1.w;
    float s = 0.f, q = 0.f;
    #pragma unroll
    for (int i = 0; i < 8; i++) { s += acc[i]; q += acc[i] * acc[i]; }
    s = wredsum(s);
    q = wredsum(q);
    float mu = s * (1.f / 256.f);
    float var = q * (1.f / 256.f) - mu * mu;
    float rs = rsqrtf(var + LN_EPS);
    float4 g0 = *(const float4*)&lng[lane * 8];
    float4 g1 = *(const float4*)&lng[lane * 8 + 4];
    float4 q0 = *(const float4*)&lnb[lane * 8];
    float4 q1 = *(const float4*)&lnb[lane * 8 + 4];
    float gg[8] = {g0.x, g0.y, g0.z, g0.w, g1.x, g1.y, g1.z, g1.w};
    float qq[8] = {q0.x, q0.y, q0.z, q0.w, q1.x, q1.y, q1.z, q1.w};
    float y[8];
    #pragma unroll
    for (int i = 0; i < 8; i++)
        y[i] = fmaxf((acc[i] - mu) * rs * gg[i] + qq[i], 0.f);
    size_t base = (size_t)d * 256 + lane * 8;
    *(float4*)&g_agg1[base]     = make_float4(y[0], y[1], y[2], y[3]);
    *(float4*)&g_agg1[base + 4] = make_float4(y[4], y[5], y[6], y[7]);
}

// -- GAT layer 2 (H=1, C=64) single-pass + bias + LN + ReLU + MLP head -----
__global__ __launch_bounds__(256) void aggregate2_kernel(
    const float* __restrict__ b2, const float* __restrict__ lng,
    const float* __restrict__ lnb,
    const float* __restrict__ fc1W, const float* __restrict__ fc1b,
    const float* __restrict__ fc2W, const float* __restrict__ fc2b,
    float* __restrict__ out, int N) {
    __shared__ float hs[8][64];
    int warp = threadIdx.x >> 5, lane = threadIdx.x & 31;
    int d = blockIdx.x * 8 + warp;
    if (d >= N) return;
    int beg = g_rowoff[d], end = g_rowoff[d + 1];
    float adv = g_ald2[d];

    float den = 0.f, acc0 = 0.f, acc1 = 0.f;
    for (int b0 = beg; b0 < end; b0 += 32) {
        int nE = min(32, end - b0);
        float w = 0.f;
        int sj = 0;
        if (lane < nE) {
            sj = g_csr[b0 + lane];
            w = __expf(lrelu(g_als2[sj] + adv));
            den += w;
        }
        for (int jj = 0; jj < nE; jj++) {
            int s = __shfl_sync(0xffffffffu, sj, jj);
            float wg = __shfl_sync(0xffffffffu, w, jj);
            float2 p = *(const float2*)&g_h2[(size_t)s * 64 + lane * 2];
            acc0 += wg * p.x;
            acc1 += wg * p.y;
        }
    }
    den = wredsum(den);
    float inv = 1.f / den;
    acc0 *= inv;
    acc1 *= inv;

    // fused: bias + LayerNorm(64) + ReLU
    float2 bv = *(const float2*)&b2[lane * 2];
    acc0 += bv.x; acc1 += bv.y;
    float s = wredsum(acc0 + acc1);
    float q = wredsum(acc0 * acc0 + acc1 * acc1);
    float mu = s * (1.f / 64.f);
    float var = q * (1.f / 64.f) - mu * mu;
    float rs = rsqrtf(var + LN_EPS);
    float2 gv = *(const float2*)&lng[lane * 2];
    float2 qv = *(const float2*)&lnb[lane * 2];
    float y0 = fmaxf((acc0 - mu) * rs * gv.x + qv.x, 0.f);
    float y1 = fmaxf((acc1 - mu) * rs * gv.y + qv.y, 0.f);

    // fused MLP head: 64 -> relu(32) -> 1
    hs[warp][lane * 2] = y0;
    hs[warp][lane * 2 + 1] = y1;
    __syncwarp();
    float a = fc1b[lane];
    #pragma unroll
    for (int k = 0; k < 64; k++) a += hs[warp][k] * fc1W[k * 32 + lane];
    a = fmaxf(a, 0.f);
    float o = wredsum(a * fc2W[lane]);
    if (lane == 0) out[d] = o + fc2b[0];
}

// ---------------- launch --------------------------------------------------
extern "C" void kernel_launch(void* const* d_in, const int* in_sizes, int n_in,
                              void* d_out, int out_size) {
    const float* x        = (const float*)d_in[0];
    const int*   ei32     = (const int*)d_in[1];
    const float* W1       = (const float*)d_in[2];
    const float* att_src1 = (const float*)d_in[3];
    const float* att_dst1 = (const float*)d_in[4];
    const float* b1       = (const float*)d_in[5];
    const float* ln1_g    = (const float*)d_in[6];
    const float* ln1_b    = (const float*)d_in[7];
    const float* W2       = (const float*)d_in[8];
    const float* att_src2 = (const float*)d_in[9];
    const float* att_dst2 = (const float*)d_in[10];
    const float* b2       = (const float*)d_in[11];
    const float* ln2_g    = (const float*)d_in[12];
    const float* ln2_b    = (const float*)d_in[13];
    const float* fc1_W    = (const float*)d_in[14];
    const float* fc1_b    = (const float*)d_in[15];
    const float* fc2_W    = (const float*)d_in[16];
    const float* fc2_b    = (const float*)d_in[17];
    float* out = (float*)d_out;

    int N = in_sizes[0] / 128;
    int E = in_sizes[1] / 2;
    int ET = E + N;

    int* p_count;
    float *p_h1, *p_agg1, *p_h2, *p_als1, *p_ald1, *p_als2, *p_ald2;
    cudaGetSymbolAddress((void**)&p_count, g_count);
    cudaGetSymbolAddress((void**)&p_h1, g_h1);
    cudaGetSymbolAddress((void**)&p_agg1, g_agg1);
    cudaGetSymbolAddress((void**)&p_h2, g_h2);
    cudaGetSymbolAddress((void**)&p_als1, g_als1);
    cudaGetSymbolAddress((void**)&p_ald1, g_ald1);
    cudaGetSymbolAddress((void**)&p_als2, g_als2);
    cudaGetSymbolAddress((void**)&p_ald2, g_ald2);

    int nwblk = (N + 7) / 8;  // warp-per-node kernels, 256 thr = 8 warps

    // --- graph prep: histogram -> scan -> scatter (CSR by dst) ---
    zero_int_kernel<<<(N + 255) / 256, 256>>>(p_count, N);
    hist_kernel<<<(ET + 255) / 256, 256>>>(ei32, E, N);
    scan_kernel<<<1, 1024>>>(N, ET);
    scatter_kernel<<<(ET + 255) / 256, 256>>>(ei32, E, N);

    // --- layer 1: h1 = x @ W1 (tf32 TC) with fused logits; agg + LN ---
    {
        dim3 grid((N + 127) / 128, 4);
        gemm_tf32_fused_kernel<<<grid, 256>>>(x, W1, p_h1,
                                              att_src1, att_dst1,
                                              p_als1, p_ald1, 4,
                                              N, 128, 256);
    }
    aggregate1_kernel<<<nwblk, 256>>>(b1, ln1_g, ln1_b, N);

    // --- layer 2: h2 = agg1 @ W2 (tf32 TC) with fused logits; agg+LN+MLP ---
    {
        dim3 grid((N + 127) / 128, 1);
        gemm_tf32_fused_kernel<<<grid, 256>>>(p_agg1, W2, p_h2,
                                              att_src2, att_dst2,
                                              p_als2, p_ald2, 1,
                                              N, 256, 64);
    }
    aggregate2_kernel<<<nwblk, 256>>>(b2, ln2_g, ln2_b,
                                      fc1_W, fc1_b, fc2_W, fc2_b, out, N);
}